// round 2
// baseline (speedup 1.0000x reference)
#include <cuda_runtime.h>
#include <float.h>

#define B_ROWS 65536
#define K_CL   1024
#define D_DIM  256
#define LR_F   0.05f

#define BM  128
#define BN  128
#define BDT 16

// ---------------- device scratch (no allocations allowed) ----------------
__device__ float  g_acc[K_CL * D_DIM];   // SOM update accumulator
__device__ float  g_c[K_CL];             // ||e_k||^2
__device__ int    g_nmin[B_ROWS];
__device__ double g_commit;
__device__ double g_som;

// ---------------- f32x2 packed-math helpers ----------------
#define FMA2(acc, a, b) asm("fma.rn.f32x2 %0, %1, %2, %0;" : "+l"(acc) : "l"(a), "l"(b))
#define PACK_BCAST(p, v) asm("mov.b64 %0, {%1, %1};" : "=l"(p) : "f"(v))
#define UNPACK2(lo, hi, p) asm("mov.b64 {%0, %1}, %2;" : "=f"(lo), "=f"(hi) : "l"(p))

// ---------------- prep: zero accumulators, compute ||e_k||^2 ----------------
__global__ void prep_kernel(const float* __restrict__ e) {
    int k = blockIdx.x;        // 1024 blocks
    int t = threadIdx.x;       // 256 threads
    int idx = k * D_DIM + t;
    g_acc[idx] = 0.0f;
    float v = e[idx];
    v = v * v;
    #pragma unroll
    for (int off = 16; off > 0; off >>= 1)
        v += __shfl_down_sync(0xffffffffu, v, off);
    __shared__ float ws[8];
    int lane = t & 31, wid = t >> 5;
    if (lane == 0) ws[wid] = v;
    __syncthreads();
    if (t == 0) {
        float s = 0.f;
        #pragma unroll
        for (int i = 0; i < 8; i++) s += ws[i];
        g_c[k] = s;
        if (k == 0) { g_commit = 0.0; g_som = 0.0; }
    }
}

// ---------------- argmin GEMM: score[b][k] = ||e_k||^2 - 2 * x_b . e_k ----------------
// Block: 128 rows x all 1024 clusters (looped in 128-wide tiles), 256 threads.
// Thread tile: 8 rows x 8 cols, accumulated as f32x2 row-pairs (FFMA2 = full-rate fp32).
__global__ __launch_bounds__(256, 2) void argmin_kernel(
    const float* __restrict__ x, const float* __restrict__ e) {

    __shared__ __align__(16) float xs[BDT][BM + 4];
    __shared__ __align__(16) float es[BDT][BN + 4];
    __shared__ float rv[BM][17];
    __shared__ int   rk[BM][17];

    const int tid = threadIdx.x;
    const int m0  = blockIdx.x * BM;
    const int ty  = tid >> 4;   // 0..15 : row group (8 rows each)
    const int tx  = tid & 15;   // 0..15 : col lane (cols tx + 16*j)

    // tile loader mapping: 128 rows x 16 floats = 512 float4, 2 per thread
    const int fA = tid, fB = tid + 256;
    const int rA = fA >> 2, cA = fA & 3;
    const int rB = fB >> 2, cB = fB & 3;

    const float* xgA = x + (size_t)(m0 + rA) * D_DIM + cA * 4;
    const float* xgB = x + (size_t)(m0 + rB) * D_DIM + cB * 4;

    float bestv[8];
    int   bestk[8];
    #pragma unroll
    for (int i = 0; i < 8; i++) { bestv[i] = FLT_MAX; bestk[i] = 0; }

    for (int n0 = 0; n0 < K_CL; n0 += BN) {
        const float* egA = e + (size_t)(n0 + rA) * D_DIM + cA * 4;
        const float* egB = e + (size_t)(n0 + rB) * D_DIM + cB * 4;

        unsigned long long acc[4][8];
        #pragma unroll
        for (int ip = 0; ip < 4; ip++)
            #pragma unroll
            for (int j = 0; j < 8; j++) acc[ip][j] = 0ULL;

        // prefetch d-tile 0
        float4 px0 = *(const float4*)(xgA);
        float4 px1 = *(const float4*)(xgB);
        float4 pe0 = *(const float4*)(egA);
        float4 pe1 = *(const float4*)(egB);

        for (int dt = 0; dt < D_DIM / BDT; dt++) {
            // stage prefetched tile into smem (d-major)
            xs[cA * 4 + 0][rA] = px0.x; xs[cA * 4 + 1][rA] = px0.y;
            xs[cA * 4 + 2][rA] = px0.z; xs[cA * 4 + 3][rA] = px0.w;
            xs[cB * 4 + 0][rB] = px1.x; xs[cB * 4 + 1][rB] = px1.y;
            xs[cB * 4 + 2][rB] = px1.z; xs[cB * 4 + 3][rB] = px1.w;
            es[cA * 4 + 0][rA] = pe0.x; es[cA * 4 + 1][rA] = pe0.y;
            es[cA * 4 + 2][rA] = pe0.z; es[cA * 4 + 3][rA] = pe0.w;
            es[cB * 4 + 0][rB] = pe1.x; es[cB * 4 + 1][rB] = pe1.y;
            es[cB * 4 + 2][rB] = pe1.z; es[cB * 4 + 3][rB] = pe1.w;
            __syncthreads();

            if (dt < D_DIM / BDT - 1) {
                int d0 = (dt + 1) * BDT;
                px0 = *(const float4*)(xgA + d0);
                px1 = *(const float4*)(xgB + d0);
                pe0 = *(const float4*)(egA + d0);
                pe1 = *(const float4*)(egB + d0);
            }

            #pragma unroll
            for (int d = 0; d < BDT; d++) {
                unsigned long long a2[4];
                #pragma unroll
                for (int ip = 0; ip < 4; ip++)
                    a2[ip] = *(const unsigned long long*)&xs[d][ty * 8 + 2 * ip];
                #pragma unroll
                for (int j = 0; j < 8; j++) {
                    unsigned long long b2;
                    PACK_BCAST(b2, es[d][tx + 16 * j]);
                    #pragma unroll
                    for (int ip = 0; ip < 4; ip++)
                        FMA2(acc[ip][j], a2[ip], b2);
                }
            }
            __syncthreads();
        }

        // epilogue: score = c[k] - 2*dot ; running argmin (k ascending => strict <)
        float cv[8];
        #pragma unroll
        for (int j = 0; j < 8; j++) cv[j] = g_c[n0 + tx + 16 * j];

        #pragma unroll
        for (int ip = 0; ip < 4; ip++) {
            #pragma unroll
            for (int j = 0; j < 8; j++) {
                float lo, hi;
                UNPACK2(lo, hi, acc[ip][j]);
                int col = n0 + tx + 16 * j;
                float s0 = cv[j] - 2.0f * lo;
                float s1 = cv[j] - 2.0f * hi;
                int i0 = 2 * ip, i1 = 2 * ip + 1;
                if (s0 < bestv[i0]) { bestv[i0] = s0; bestk[i0] = col; }
                if (s1 < bestv[i1]) { bestv[i1] = s1; bestk[i1] = col; }
            }
        }
    }

    // cross-thread argmin reduction (16 candidates per row), tie -> lowest k
    #pragma unroll
    for (int i = 0; i < 8; i++) {
        int row = ty * 8 + i;
        rv[row][tx] = bestv[i];
        rk[row][tx] = bestk[i];
    }
    __syncthreads();
    if (tid < BM) {
        int row = tid;
        float bv = rv[row][0];
        int   bk = rk[row][0];
        #pragma unroll
        for (int t = 1; t < 16; t++) {
            float v = rv[row][t]; int k = rk[row][t];
            if (v < bv || (v == bv && k < bk)) { bv = v; bk = k; }
        }
        g_nmin[m0 + row] = bk;
    }
}

// ---------------- phase B: z_q gather, losses, SOM scatter (atomics) ----------------
__global__ void phaseb_kernel(const float* __restrict__ x, const float* __restrict__ e,
                              float* __restrict__ out) {
    const int warp = threadIdx.x >> 5;
    const int lane = threadIdx.x & 31;
    const int b = blockIdx.x * 8 + warp;

    int n  = g_nmin[b];
    int nx = n >> 5, ny = n & 31;
    int iu  = (nx < 31 ? nx + 1 : nx) * 32 + ny;
    int idn = (nx > 0  ? nx - 1 : nx) * 32 + ny;
    int il  = nx * 32 + (ny > 0  ? ny - 1 : ny);
    int ir  = nx * 32 + (ny < 31 ? ny + 1 : ny);
    int nbrs[4] = {iu, idn, il, ir};

    const float4* xr = (const float4*)(x + (size_t)b * D_DIM);
    const float4* zr = (const float4*)(e + (size_t)n * D_DIM);
    float4* zout = (float4*)out + (size_t)b * (D_DIM / 4);

    float commit = 0.f, som = 0.f;

    #pragma unroll
    for (int it = 0; it < 2; it++) {
        int q = lane + it * 32;                 // 0..63 float4 per row
        float4 xv = xr[q];
        float4 zq = zr[q];
        zout[q] = zq;
        float4 dw = make_float4(xv.x - zq.x, xv.y - zq.y, xv.z - zq.z, xv.w - zq.w);
        commit += dw.x * dw.x + dw.y * dw.y + dw.z * dw.z + dw.w * dw.w;

        int base = n * D_DIM + q * 4;
        atomicAdd(&g_acc[base + 0], dw.x);
        atomicAdd(&g_acc[base + 1], dw.y);
        atomicAdd(&g_acc[base + 2], dw.z);
        atomicAdd(&g_acc[base + 3], dw.w);

        #pragma unroll
        for (int t = 0; t < 4; t++) {
            int nb = nbrs[t];
            float4 ev = ((const float4*)(e + (size_t)nb * D_DIM))[q];
            float d0 = xv.x - ev.x, d1 = xv.y - ev.y, d2 = xv.z - ev.z, d3 = xv.w - ev.w;
            som += d0 * d0 + d1 * d1 + d2 * d2 + d3 * d3;
            int nbase = nb * D_DIM + q * 4;
            atomicAdd(&g_acc[nbase + 0], 0.5f * dw.x);
            atomicAdd(&g_acc[nbase + 1], 0.5f * dw.y);
            atomicAdd(&g_acc[nbase + 2], 0.5f * dw.z);
            atomicAdd(&g_acc[nbase + 3], 0.5f * dw.w);
        }
    }

    #pragma unroll
    for (int off = 16; off > 0; off >>= 1) {
        commit += __shfl_down_sync(0xffffffffu, commit, off);
        som    += __shfl_down_sync(0xffffffffu, som, off);
    }
    if (lane == 0) {
        atomicAdd(&g_commit, (double)commit);
        atomicAdd(&g_som, (double)som);
    }
}

// ---------------- finalize: new_embeddings + scalar losses ----------------
__global__ void finalize_kernel(const float* __restrict__ e, float* __restrict__ out) {
    const size_t OFF = (size_t)B_ROWS * D_DIM;
    int i = blockIdx.x * 256 + threadIdx.x;   // K*D threads
    out[OFF + 2 + i] = e[i] + LR_F * g_acc[i];
    if (i == 0) {
        out[OFF]     = (float)(g_commit / ((double)B_ROWS * (double)D_DIM));
        out[OFF + 1] = (float)(g_som / ((double)B_ROWS * 4.0 * (double)D_DIM));
    }
}

// ---------------- launch ----------------
extern "C" void kernel_launch(void* const* d_in, const int* in_sizes, int n_in,
                              void* d_out, int out_size) {
    const float* x = (const float*)d_in[0];
    const float* e = (const float*)d_in[1];
    float* out = (float*)d_out;

    prep_kernel<<<K_CL, 256>>>(e);
    argmin_kernel<<<B_ROWS / BM, 256>>>(x, e);
    phaseb_kernel<<<B_ROWS / 8, 256>>>(x, e, out);
    finalize_kernel<<<K_CL * D_DIM / 256, 256>>>(e, out);
}

// round 8
// speedup vs baseline: 1.1447x; 1.1447x over previous
#include <cuda_runtime.h>
#include <cuda_bf16.h>
#include <float.h>
#include <stdint.h>

#define B_ROWS 65536
#define K_CL   1024
#define D_DIM  256
#define LR_F   0.05f

#define TM     128        // CTA M tile
#define TN     128        // CTA N tile
#define NT     (K_CL / TN)   // 8 N-tiles
#define NCHUNK 24         // 3 segments x 8 chunks of K=32 bf16
#define ROWB   80         // padded smem row: 32 bf16 = 64B -> 80B (conflict-free LDSM)
#define ATILE  (TM * ROWB)          // 10240 B
#define SMEMD  (4 * ATILE)          // A0,A1,B0,B1 = 40960 B

// ---------------- device scratch ----------------
__device__ float          g_acc[K_CL * D_DIM];
__device__ float          g_c[K_CL];
__device__ int            g_nmin[B_ROWS];
__device__ double         g_commit;
__device__ double         g_som;
__device__ __nv_bfloat16  g_xh[B_ROWS * D_DIM];
__device__ __nv_bfloat16  g_xl[B_ROWS * D_DIM];
__device__ __nv_bfloat16  g_eh[K_CL * D_DIM];
__device__ __nv_bfloat16  g_el[K_CL * D_DIM];
__device__ float4         g_cand[(size_t)B_ROWS * NT * 2];   // top-4 per (row, tile)

// ---------------- helpers ----------------
__device__ __forceinline__ uint32_t smem_u32(const void* p) {
    uint32_t a;
    asm("{ .reg .u64 t; cvta.to.shared.u64 t, %1; cvt.u32.u64 %0, t; }" : "=r"(a) : "l"(p));
    return a;
}
__device__ __forceinline__ void ldsm4(uint32_t* r, uint32_t addr) {
    asm volatile("ldmatrix.sync.aligned.m8n8.x4.shared.b16 {%0,%1,%2,%3}, [%4];"
        : "=r"(r[0]), "=r"(r[1]), "=r"(r[2]), "=r"(r[3]) : "r"(addr));
}
__device__ __forceinline__ void mma_bf16(float* c, const uint32_t* a, const uint32_t* b) {
    asm volatile("mma.sync.aligned.m16n8k16.row.col.f32.bf16.bf16.f32 "
        "{%0,%1,%2,%3}, {%4,%5,%6,%7}, {%8,%9}, {%0,%1,%2,%3};"
        : "+f"(c[0]), "+f"(c[1]), "+f"(c[2]), "+f"(c[3])
        : "r"(a[0]), "r"(a[1]), "r"(a[2]), "r"(a[3]), "r"(b[0]), "r"(b[1]));
}
__device__ __forceinline__ bool lessc(float a, int ka, float b, int kb) {
    return a < b || (a == b && ka < kb);
}
// sorted insert into top-4 (ascending)
__device__ __forceinline__ void ins4(float* v, int* k, float nv, int nk) {
    if (!lessc(nv, nk, v[3], k[3])) return;
    v[3] = nv; k[3] = nk;
    #pragma unroll
    for (int i = 3; i > 0; i--) {
        if (lessc(v[i], k[i], v[i - 1], k[i - 1])) {
            float tv = v[i]; v[i] = v[i - 1]; v[i - 1] = tv;
            int tk = k[i]; k[i] = k[i - 1]; k[i - 1] = tk;
        }
    }
}
__device__ __forceinline__ const __nv_bfloat16* a_src(int c) { return c < 16 ? g_xh : g_xl; }
__device__ __forceinline__ const __nv_bfloat16* b_src(int c) {
    return (c >= 8 && c < 16) ? g_el : g_eh;
}

// ---------------- prep: zero acc, c[k]=||e_k||^2, split e ----------------
__global__ void prep_kernel(const float* __restrict__ e) {
    int k = blockIdx.x, t = threadIdx.x;
    int idx = k * D_DIM + t;
    g_acc[idx] = 0.0f;
    float v = e[idx];
    __nv_bfloat16 hi = __float2bfloat16_rn(v);
    g_eh[idx] = hi;
    g_el[idx] = __float2bfloat16_rn(v - __bfloat162float(hi));
    float sq = v * v;
    #pragma unroll
    for (int off = 16; off > 0; off >>= 1)
        sq += __shfl_down_sync(0xffffffffu, sq, off);
    __shared__ float ws[8];
    int lane = t & 31, wid = t >> 5;
    if (lane == 0) ws[wid] = sq;
    __syncthreads();
    if (t == 0) {
        float s = 0.f;
        #pragma unroll
        for (int i = 0; i < 8; i++) s += ws[i];
        g_c[k] = s;
        if (k == 0) { g_commit = 0.0; g_som = 0.0; }
    }
}

// ---------------- convert x to bf16 hi/lo ----------------
__global__ void convx_kernel(const float* __restrict__ x) {
    int i = blockIdx.x * 256 + threadIdx.x;          // float4 index
    float4 v = ((const float4*)x)[i];
    __nv_bfloat16 h0 = __float2bfloat16_rn(v.x), h1 = __float2bfloat16_rn(v.y);
    __nv_bfloat16 h2 = __float2bfloat16_rn(v.z), h3 = __float2bfloat16_rn(v.w);
    __nv_bfloat16 l0 = __float2bfloat16_rn(v.x - __bfloat162float(h0));
    __nv_bfloat16 l1 = __float2bfloat16_rn(v.y - __bfloat162float(h1));
    __nv_bfloat16 l2 = __float2bfloat16_rn(v.z - __bfloat162float(h2));
    __nv_bfloat16 l3 = __float2bfloat16_rn(v.w - __bfloat162float(h3));
    __nv_bfloat162* xh2 = (__nv_bfloat162*)g_xh;
    __nv_bfloat162* xl2 = (__nv_bfloat162*)g_xl;
    xh2[i * 2]     = __halves2bfloat162(h0, h1);
    xh2[i * 2 + 1] = __halves2bfloat162(h2, h3);
    xl2[i * 2]     = __halves2bfloat162(l0, l1);
    xl2[i * 2 + 1] = __halves2bfloat162(l2, l3);
}

// ---------------- mma.sync GEMM + top-4 argmin epilogue ----------------
// grid (NT, B_ROWS/TM) = (8, 512); 256 threads; warp grid 2(M) x 4(N), warp tile 64x32.
__global__ __launch_bounds__(256, 2) void gemm_argmin_kernel() {
    extern __shared__ __align__(128) char dsm[];
    __shared__ float cs[TN];

    const int tid = threadIdx.x;
    const int lane = tid & 31, wid = tid >> 5;
    const int wr = wid >> 2, wc = wid & 3;
    const int nt = blockIdx.x, n0 = nt * TN;
    const int m0 = blockIdx.y * TM;
    const uint32_t sb = smem_u32(dsm);

    if (tid < TN) cs[tid] = g_c[n0 + tid];

    // staging: 128 rows x 4 x uint4 per tile; thread does rows (tid>>2) and +64
    const int srow = tid >> 2, sq = tid & 3;

    // ldmatrix per-lane byte offsets within a tile
    const uint32_t aoff = (uint32_t)((wr * 64 + (lane & 15)) * ROWB + (lane >> 4) * 16);
    const uint32_t boff = (uint32_t)((wc * 32 + (lane & 7) + ((lane & 16) ? 8 : 0)) * ROWB
                                     + ((lane & 8) ? 16 : 0));

    float c[4][4][4];
    #pragma unroll
    for (int mi = 0; mi < 4; mi++)
        #pragma unroll
        for (int g = 0; g < 4; g++)
            #pragma unroll
            for (int e2 = 0; e2 < 4; e2++) c[mi][g][e2] = 0.f;

    // stage chunk 0 directly
    {
        const __nv_bfloat16* A = a_src(0);
        const __nv_bfloat16* Bv = b_src(0);
        #pragma unroll
        for (int i = 0; i < 2; i++) {
            int r = srow + i * 64;
            uint4 va = *(const uint4*)(A + (size_t)(m0 + r) * D_DIM + sq * 8);
            *(uint4*)(dsm + r * ROWB + sq * 16) = va;
            uint4 vb = *(const uint4*)(Bv + (size_t)(n0 + r) * D_DIM + sq * 8);
            *(uint4*)(dsm + 2 * ATILE + r * ROWB + sq * 16) = vb;
        }
    }
    __syncthreads();

    uint4 pa[2], pb[2];
    for (int ck = 0; ck < NCHUNK; ck++) {
        const int buf = ck & 1;

        if (ck < NCHUNK - 1) {
            const __nv_bfloat16* A = a_src(ck + 1);
            const __nv_bfloat16* Bv = b_src(ck + 1);
            const int d0 = ((ck + 1) & 7) * 32;
            #pragma unroll
            for (int i = 0; i < 2; i++) {
                int r = srow + i * 64;
                pa[i] = *(const uint4*)(A + (size_t)(m0 + r) * D_DIM + d0 + sq * 8);
                pb[i] = *(const uint4*)(Bv + (size_t)(n0 + r) * D_DIM + d0 + sq * 8);
            }
        }

        const uint32_t aAdr = sb + buf * ATILE + aoff;
        const uint32_t bAdr = sb + 2 * ATILE + buf * ATILE + boff;
        #pragma unroll
        for (int kj = 0; kj < 2; kj++) {
            uint32_t af[4][4], bfr[2][4];
            #pragma unroll
            for (int mi = 0; mi < 4; mi++) ldsm4(af[mi], aAdr + mi * 16 * ROWB + kj * 32);
            #pragma unroll
            for (int gp = 0; gp < 2; gp++) ldsm4(bfr[gp], bAdr + gp * 16 * ROWB + kj * 32);
            #pragma unroll
            for (int mi = 0; mi < 4; mi++)
                #pragma unroll
                for (int g = 0; g < 4; g++)
                    mma_bf16(c[mi][g], af[mi], &bfr[g >> 1][(g & 1) * 2]);
        }

        if (ck < NCHUNK - 1) {
            const int nb = (ck + 1) & 1;
            #pragma unroll
            for (int i = 0; i < 2; i++) {
                int r = srow + i * 64;
                *(uint4*)(dsm + nb * ATILE + r * ROWB + sq * 16) = pa[i];
                *(uint4*)(dsm + 2 * ATILE + nb * ATILE + r * ROWB + sq * 16) = pb[i];
            }
        }
        __syncthreads();
    }

    // ---- epilogue: per-row top-4 over this CTA's 128 cols ----
    float2* red = (float2*)dsm;   // [128 rows][4 wc][4 entries] — tiles are dead now

    #pragma unroll
    for (int mi = 0; mi < 4; mi++) {
        #pragma unroll
        for (int half = 0; half < 2; half++) {
            int rloc = wr * 64 + mi * 16 + (lane >> 2) + half * 8;
            float v4[4]; int k4[4];
            #pragma unroll
            for (int i = 0; i < 4; i++) { v4[i] = FLT_MAX; k4[i] = 0x7fffffff; }
            #pragma unroll
            for (int g = 0; g < 4; g++) {
                #pragma unroll
                for (int e2 = 0; e2 < 2; e2++) {
                    int col = wc * 32 + g * 8 + (lane & 3) * 2 + e2;
                    float s = cs[col] - 2.0f * c[mi][g][half * 2 + e2];
                    ins4(v4, k4, s, n0 + col);
                }
            }
            #pragma unroll
            for (int off = 1; off <= 2; off <<= 1) {
                float ov[4]; int ok[4];
                #pragma unroll
                for (int i = 0; i < 4; i++) {
                    ov[i] = __shfl_xor_sync(0xffffffffu, v4[i], off);
                    ok[i] = __shfl_xor_sync(0xffffffffu, k4[i], off);
                }
                #pragma unroll
                for (int i = 0; i < 4; i++) ins4(v4, k4, ov[i], ok[i]);
            }
            if ((lane & 3) == 0) {
                #pragma unroll
                for (int i = 0; i < 4; i++)
                    red[(rloc * 4 + wc) * 4 + i] = make_float2(v4[i], __int_as_float(k4[i]));
            }
        }
    }
    __syncthreads();

    if (tid < TM) {
        float v4[4]; int k4[4];
        #pragma unroll
        for (int i = 0; i < 4; i++) { v4[i] = FLT_MAX; k4[i] = 0x7fffffff; }
        #pragma unroll
        for (int w = 0; w < 4; w++)
            #pragma unroll
            for (int p = 0; p < 4; p++) {
                float2 t = red[(tid * 4 + w) * 4 + p];
                ins4(v4, k4, t.x, __float_as_int(t.y));
            }
        size_t base = ((size_t)(m0 + tid) * NT + nt) * 2;
        g_cand[base] = make_float4(v4[0], __int_as_float(k4[0]),
                                   v4[1], __int_as_float(k4[1]));
        g_cand[base + 1] = make_float4(v4[2], __int_as_float(k4[2]),
                                       v4[3], __int_as_float(k4[3]));
    }
}

// ---------------- select: global argmin, near-ties rescored in EXACT fp32 ----------------
// Rescore arithmetic deliberately bit-matches the known-passing full-fp32 kernel:
// dot = sequential fmaf chain over d; score = g_c[k] - 2*dot; pick lowest (tie -> lowest k).
#define MARGIN 0.05f
#define NCAND (4 * NT)
__global__ void select_kernel(const float* __restrict__ x, const float* __restrict__ e) {
    int b = blockIdx.x * 256 + threadIdx.x;
    float v[NCAND]; int kk[NCAND];
    #pragma unroll
    for (int t = 0; t < NT; t++) {
        float4 c0 = g_cand[((size_t)b * NT + t) * 2];
        float4 c1 = g_cand[((size_t)b * NT + t) * 2 + 1];
        v[4 * t + 0] = c0.x; kk[4 * t + 0] = __float_as_int(c0.y);
        v[4 * t + 1] = c0.z; kk[4 * t + 1] = __float_as_int(c0.w);
        v[4 * t + 2] = c1.x; kk[4 * t + 2] = __float_as_int(c1.y);
        v[4 * t + 3] = c1.z; kk[4 * t + 3] = __float_as_int(c1.w);
    }
    float bv = v[0]; int bk = kk[0];
    #pragma unroll
    for (int i = 1; i < NCAND; i++)
        if (v[i] < bv || (v[i] == bv && kk[i] < bk)) { bv = v[i]; bk = kk[i]; }
    int cnt = 0;
    #pragma unroll
    for (int i = 0; i < NCAND; i++) if (v[i] <= bv + MARGIN) cnt++;
    if (cnt > 1) {
        float bs = FLT_MAX; int bki = 0x7fffffff;
        for (int i = 0; i < NCAND; i++) {
            if (v[i] > bv + MARGIN) continue;
            int k = kk[i];
            bool dup = false;
            for (int j = 0; j < i; j++)
                if (v[j] <= bv + MARGIN && kk[j] == k) { dup = true; break; }
            if (dup) continue;
            float dot = 0.0f;
            const float* xr = x + (size_t)b * D_DIM;
            const float* er = e + (size_t)k * D_DIM;
            #pragma unroll 8
            for (int d = 0; d < D_DIM; d++) dot = fmaf(xr[d], er[d], dot);
            float s = g_c[k] - 2.0f * dot;
            if (s < bs || (s == bs && k < bki)) { bs = s; bki = k; }
        }
        bk = bki;
    }
    g_nmin[b] = bk;
}

// ---------------- phase B: z_q gather, losses, SOM scatter (atomics) ----------------
__global__ void phaseb_kernel(const float* __restrict__ x, const float* __restrict__ e,
                              float* __restrict__ out) {
    const int warp = threadIdx.x >> 5;
    const int lane = threadIdx.x & 31;
    const int b = blockIdx.x * 8 + warp;

    int n  = g_nmin[b];
    int nx = n >> 5, ny = n & 31;
    int iu  = (nx < 31 ? nx + 1 : nx) * 32 + ny;
    int idn = (nx > 0  ? nx - 1 : nx) * 32 + ny;
    int il  = nx * 32 + (ny > 0  ? ny - 1 : ny);
    int ir  = nx * 32 + (ny < 31 ? ny + 1 : ny);
    int nbrs[4] = {iu, idn, il, ir};

    const float4* xr = (const float4*)(x + (size_t)b * D_DIM);
    const float4* zr = (const float4*)(e + (size_t)n * D_DIM);
    float4* zout = (float4*)out + (size_t)b * (D_DIM / 4);

    float commit = 0.f, som = 0.f;

    #pragma unroll
    for (int it = 0; it < 2; it++) {
        int q = lane + it * 32;
        float4 xv = xr[q];
        float4 zq = zr[q];
        zout[q] = zq;
        float4 dw = make_float4(xv.x - zq.x, xv.y - zq.y, xv.z - zq.z, xv.w - zq.w);
        commit += dw.x * dw.x + dw.y * dw.y + dw.z * dw.z + dw.w * dw.w;

        int base = n * D_DIM + q * 4;
        atomicAdd(&g_acc[base + 0], dw.x);
        atomicAdd(&g_acc[base + 1], dw.y);
        atomicAdd(&g_acc[base + 2], dw.z);
        atomicAdd(&g_acc[base + 3], dw.w);

        #pragma unroll
        for (int t = 0; t < 4; t++) {
            int nb = nbrs[t];
            float4 ev = ((const float4*)(e + (size_t)nb * D_DIM))[q];
            float d0 = xv.x - ev.x, d1 = xv.y - ev.y, d2 = xv.z - ev.z, d3 = xv.w - ev.w;
            som += d0 * d0 + d1 * d1 + d2 * d2 + d3 * d3;
            int nbase = nb * D_DIM + q * 4;
            atomicAdd(&g_acc[nbase + 0], 0.5f * dw.x);
            atomicAdd(&g_acc[nbase + 1], 0.5f * dw.y);
            atomicAdd(&g_acc[nbase + 2], 0.5f * dw.z);
            atomicAdd(&g_acc[nbase + 3], 0.5f * dw.w);
        }
    }

    #pragma unroll
    for (int off = 16; off > 0; off >>= 1) {
        commit += __shfl_down_sync(0xffffffffu, commit, off);
        som    += __shfl_down_sync(0xffffffffu, som, off);
    }
    if (lane == 0) {
        atomicAdd(&g_commit, (double)commit);
        atomicAdd(&g_som, (double)som);
    }
}

// ---------------- finalize ----------------
__global__ void finalize_kernel(const float* __restrict__ e, float* __restrict__ out) {
    const size_t OFF = (size_t)B_ROWS * D_DIM;
    int i = blockIdx.x * 256 + threadIdx.x;
    out[OFF + 2 + i] = e[i] + LR_F * g_acc[i];
    if (i == 0) {
        out[OFF]     = (float)(g_commit / ((double)B_ROWS * (double)D_DIM));
        out[OFF + 1] = (float)(g_som / ((double)B_ROWS * 4.0 * (double)D_DIM));
    }
}

// ---------------- launch ----------------
extern "C" void kernel_launch(void* const* d_in, const int* in_sizes, int n_in,
                              void* d_out, int out_size) {
    const float* x = (const float*)d_in[0];
    const float* e = (const float*)d_in[1];
    float* out = (float*)d_out;

    prep_kernel<<<K_CL, 256>>>(e);
    convx_kernel<<<B_ROWS * D_DIM / 4 / 256, 256>>>(x);
    dim3 ggrid(NT, B_ROWS / TM);
    gemm_argmin_kernel<<<ggrid, 256, SMEMD>>>();
    select_kernel<<<B_ROWS / 256, 256>>>(x, e);
    phaseb_kernel<<<B_ROWS / 8, 256>>>(x, e, out);
    finalize_kernel<<<K_CL * D_DIM / 256, 256>>>(e, out);
}

// round 9
// speedup vs baseline: 1.8973x; 1.6575x over previous
#include <cuda_runtime.h>
#include <cuda_bf16.h>
#include <float.h>
#include <stdint.h>

#define B_ROWS 65536
#define K_CL   1024
#define D_DIM  256
#define LR_F   0.05f

#define TM     128        // CTA M tile
#define TN     128        // CTA N tile
#define NT     (K_CL / TN)   // 8 N-tiles
#define NCHUNK 24         // 3 segments x 8 chunks of K=32 bf16
#define ROWB   80         // padded smem row: 32 bf16 = 64B -> 80B (conflict-free LDSM)
#define ATILE  (TM * ROWB)          // 10240 B
#define SMEMD  (4 * ATILE)          // A0,A1,B0,B1 = 40960 B

// ---------------- device scratch ----------------
__device__ float          g_sumx[K_CL * D_DIM];   // per-cluster sum of x
__device__ int            g_cnt[K_CL];            // per-cluster row count
__device__ float          g_c[K_CL];              // ||e_k||^2
__device__ int            g_nmin[B_ROWS];
__device__ double         g_commit;
__device__ double         g_som;
__device__ __nv_bfloat16  g_xh[B_ROWS * D_DIM];
__device__ __nv_bfloat16  g_xl[B_ROWS * D_DIM];
__device__ __nv_bfloat16  g_eh[K_CL * D_DIM];
__device__ __nv_bfloat16  g_el[K_CL * D_DIM];
__device__ float4         g_cand[(size_t)B_ROWS * NT];   // top-2 per (row, tile)

// ---------------- helpers ----------------
__device__ __forceinline__ uint32_t smem_u32(const void* p) {
    uint32_t a;
    asm("{ .reg .u64 t; cvta.to.shared.u64 t, %1; cvt.u32.u64 %0, t; }" : "=r"(a) : "l"(p));
    return a;
}
__device__ __forceinline__ void ldsm4(uint32_t* r, uint32_t addr) {
    asm volatile("ldmatrix.sync.aligned.m8n8.x4.shared.b16 {%0,%1,%2,%3}, [%4];"
        : "=r"(r[0]), "=r"(r[1]), "=r"(r[2]), "=r"(r[3]) : "r"(addr));
}
__device__ __forceinline__ void mma_bf16(float* c, const uint32_t* a, const uint32_t* b) {
    asm volatile("mma.sync.aligned.m16n8k16.row.col.f32.bf16.bf16.f32 "
        "{%0,%1,%2,%3}, {%4,%5,%6,%7}, {%8,%9}, {%0,%1,%2,%3};"
        : "+f"(c[0]), "+f"(c[1]), "+f"(c[2]), "+f"(c[3])
        : "r"(a[0]), "r"(a[1]), "r"(a[2]), "r"(a[3]), "r"(b[0]), "r"(b[1]));
}
__device__ __forceinline__ bool lessc(float a, int ka, float b, int kb) {
    return a < b || (a == b && ka < kb);
}
__device__ __forceinline__ void merge2(float& bv, int& bk, float& sv, int& sk,
                                       float v, int k) {
    if (lessc(v, k, bv, bk)) { sv = bv; sk = bk; bv = v; bk = k; }
    else if (lessc(v, k, sv, sk)) { sv = v; sk = k; }
}
__device__ __forceinline__ const __nv_bfloat16* a_src(int c) { return c < 16 ? g_xh : g_xl; }
__device__ __forceinline__ const __nv_bfloat16* b_src(int c) {
    return (c >= 8 && c < 16) ? g_el : g_eh;
}

// ---------------- prep: zero sumx/cnt, c[k]=||e_k||^2, split e ----------------
__global__ void prep_kernel(const float* __restrict__ e) {
    int k = blockIdx.x, t = threadIdx.x;
    int idx = k * D_DIM + t;
    g_sumx[idx] = 0.0f;
    float v = e[idx];
    __nv_bfloat16 hi = __float2bfloat16_rn(v);
    g_eh[idx] = hi;
    g_el[idx] = __float2bfloat16_rn(v - __bfloat162float(hi));
    float sq = v * v;
    #pragma unroll
    for (int off = 16; off > 0; off >>= 1)
        sq += __shfl_down_sync(0xffffffffu, sq, off);
    __shared__ float ws[8];
    int lane = t & 31, wid = t >> 5;
    if (lane == 0) ws[wid] = sq;
    __syncthreads();
    if (t == 0) {
        float s = 0.f;
        #pragma unroll
        for (int i = 0; i < 8; i++) s += ws[i];
        g_c[k] = s;
        g_cnt[k] = 0;
        if (k == 0) { g_commit = 0.0; g_som = 0.0; }
    }
}

// ---------------- convert x to bf16 hi/lo ----------------
__global__ void convx_kernel(const float* __restrict__ x) {
    int i = blockIdx.x * 256 + threadIdx.x;          // float4 index
    float4 v = ((const float4*)x)[i];
    __nv_bfloat16 h0 = __float2bfloat16_rn(v.x), h1 = __float2bfloat16_rn(v.y);
    __nv_bfloat16 h2 = __float2bfloat16_rn(v.z), h3 = __float2bfloat16_rn(v.w);
    __nv_bfloat16 l0 = __float2bfloat16_rn(v.x - __bfloat162float(h0));
    __nv_bfloat16 l1 = __float2bfloat16_rn(v.y - __bfloat162float(h1));
    __nv_bfloat16 l2 = __float2bfloat16_rn(v.z - __bfloat162float(h2));
    __nv_bfloat16 l3 = __float2bfloat16_rn(v.w - __bfloat162float(h3));
    __nv_bfloat162* xh2 = (__nv_bfloat162*)g_xh;
    __nv_bfloat162* xl2 = (__nv_bfloat162*)g_xl;
    xh2[i * 2]     = __halves2bfloat162(h0, h1);
    xh2[i * 2 + 1] = __halves2bfloat162(h2, h3);
    xl2[i * 2]     = __halves2bfloat162(l0, l1);
    xl2[i * 2 + 1] = __halves2bfloat162(l2, l3);
}

// ---------------- mma.sync GEMM + top-2 argmin epilogue ----------------
// grid (NT, B_ROWS/TM) = (8, 512); 256 threads; warp grid 2(M) x 4(N), warp tile 64x32.
__global__ __launch_bounds__(256, 2) void gemm_argmin_kernel() {
    extern __shared__ __align__(128) char dsm[];
    __shared__ float cs[TN];

    const int tid = threadIdx.x;
    const int lane = tid & 31, wid = tid >> 5;
    const int wr = wid >> 2, wc = wid & 3;
    const int nt = blockIdx.x, n0 = nt * TN;
    const int m0 = blockIdx.y * TM;
    const uint32_t sb = smem_u32(dsm);

    if (tid < TN) cs[tid] = g_c[n0 + tid];

    // staging: 128 rows x 4 x uint4 per tile; thread does rows (tid>>2) and +64
    const int srow = tid >> 2, sq = tid & 3;

    // ldmatrix per-lane byte offsets within a tile
    const uint32_t aoff = (uint32_t)((wr * 64 + (lane & 15)) * ROWB + (lane >> 4) * 16);
    const uint32_t boff = (uint32_t)((wc * 32 + (lane & 7) + ((lane & 16) ? 8 : 0)) * ROWB
                                     + ((lane & 8) ? 16 : 0));

    float c[4][4][4];
    #pragma unroll
    for (int mi = 0; mi < 4; mi++)
        #pragma unroll
        for (int g = 0; g < 4; g++)
            #pragma unroll
            for (int e2 = 0; e2 < 4; e2++) c[mi][g][e2] = 0.f;

    // stage chunk 0 directly
    {
        const __nv_bfloat16* A = a_src(0);
        const __nv_bfloat16* Bv = b_src(0);
        #pragma unroll
        for (int i = 0; i < 2; i++) {
            int r = srow + i * 64;
            uint4 va = *(const uint4*)(A + (size_t)(m0 + r) * D_DIM + sq * 8);
            *(uint4*)(dsm + r * ROWB + sq * 16) = va;
            uint4 vb = *(const uint4*)(Bv + (size_t)(n0 + r) * D_DIM + sq * 8);
            *(uint4*)(dsm + 2 * ATILE + r * ROWB + sq * 16) = vb;
        }
    }
    __syncthreads();

    uint4 pa[2], pb[2];
    for (int ck = 0; ck < NCHUNK; ck++) {
        const int buf = ck & 1;

        if (ck < NCHUNK - 1) {
            const __nv_bfloat16* A = a_src(ck + 1);
            const __nv_bfloat16* Bv = b_src(ck + 1);
            const int d0 = ((ck + 1) & 7) * 32;
            #pragma unroll
            for (int i = 0; i < 2; i++) {
                int r = srow + i * 64;
                pa[i] = *(const uint4*)(A + (size_t)(m0 + r) * D_DIM + d0 + sq * 8);
                pb[i] = *(const uint4*)(Bv + (size_t)(n0 + r) * D_DIM + d0 + sq * 8);
            }
        }

        const uint32_t aAdr = sb + buf * ATILE + aoff;
        const uint32_t bAdr = sb + 2 * ATILE + buf * ATILE + boff;
        #pragma unroll
        for (int kj = 0; kj < 2; kj++) {
            uint32_t af[4][4], bfr[2][4];
            #pragma unroll
            for (int mi = 0; mi < 4; mi++) ldsm4(af[mi], aAdr + mi * 16 * ROWB + kj * 32);
            #pragma unroll
            for (int gp = 0; gp < 2; gp++) ldsm4(bfr[gp], bAdr + gp * 16 * ROWB + kj * 32);
            #pragma unroll
            for (int mi = 0; mi < 4; mi++)
                #pragma unroll
                for (int g = 0; g < 4; g++)
                    mma_bf16(c[mi][g], af[mi], &bfr[g >> 1][(g & 1) * 2]);
        }

        if (ck < NCHUNK - 1) {
            const int nb = (ck + 1) & 1;
            #pragma unroll
            for (int i = 0; i < 2; i++) {
                int r = srow + i * 64;
                *(uint4*)(dsm + nb * ATILE + r * ROWB + sq * 16) = pa[i];
                *(uint4*)(dsm + 2 * ATILE + nb * ATILE + r * ROWB + sq * 16) = pb[i];
            }
        }
        __syncthreads();
    }

    // ---- epilogue: per-row top-2 over this CTA's 128 cols ----
    float2* red = (float2*)dsm;   // [128 rows][4 wc][2 entries] — tiles are dead now

    #pragma unroll
    for (int mi = 0; mi < 4; mi++) {
        #pragma unroll
        for (int half = 0; half < 2; half++) {
            int rloc = wr * 64 + mi * 16 + (lane >> 2) + half * 8;
            float bv = FLT_MAX, sv = FLT_MAX;
            int bk = 0x7fffffff, sk = 0x7fffffff;
            #pragma unroll
            for (int g = 0; g < 4; g++) {
                #pragma unroll
                for (int e2 = 0; e2 < 2; e2++) {
                    int col = wc * 32 + g * 8 + (lane & 3) * 2 + e2;
                    float s = cs[col] - 2.0f * c[mi][g][half * 2 + e2];
                    merge2(bv, bk, sv, sk, s, n0 + col);
                }
            }
            #pragma unroll
            for (int off = 1; off <= 2; off <<= 1) {
                float obv = __shfl_xor_sync(0xffffffffu, bv, off);
                int   obk = __shfl_xor_sync(0xffffffffu, bk, off);
                float osv = __shfl_xor_sync(0xffffffffu, sv, off);
                int   osk = __shfl_xor_sync(0xffffffffu, sk, off);
                merge2(bv, bk, sv, sk, obv, obk);
                merge2(bv, bk, sv, sk, osv, osk);
            }
            if ((lane & 3) == 0) {
                red[(rloc * 4 + wc) * 2 + 0] = make_float2(bv, __int_as_float(bk));
                red[(rloc * 4 + wc) * 2 + 1] = make_float2(sv, __int_as_float(sk));
            }
        }
    }
    __syncthreads();

    if (tid < TM) {
        float bv = FLT_MAX, sv = FLT_MAX;
        int bk = 0x7fffffff, sk = 0x7fffffff;
        #pragma unroll
        for (int w = 0; w < 4; w++)
            #pragma unroll
            for (int p = 0; p < 2; p++) {
                float2 t = red[(tid * 4 + w) * 2 + p];
                merge2(bv, bk, sv, sk, t.x, __float_as_int(t.y));
            }
        g_cand[(size_t)(m0 + tid) * NT + nt] =
            make_float4(bv, __int_as_float(bk), sv, __int_as_float(sk));
    }
}

// ---------------- select: global argmin, near-ties rescored in EXACT fp32 ----------------
// Rescore arithmetic bit-matches the known-passing full-fp32 kernel:
// dot = sequential fmaf chain; score = g_c[k] - 2*dot; lowest (tie -> lowest k).
#define MARGIN 0.05f
#define NCAND (2 * NT)
__global__ void select_kernel(const float* __restrict__ x, const float* __restrict__ e) {
    int b = blockIdx.x * 256 + threadIdx.x;
    float v[NCAND]; int kk[NCAND];
    #pragma unroll
    for (int t = 0; t < NT; t++) {
        float4 c0 = g_cand[(size_t)b * NT + t];
        v[2 * t + 0] = c0.x; kk[2 * t + 0] = __float_as_int(c0.y);
        v[2 * t + 1] = c0.z; kk[2 * t + 1] = __float_as_int(c0.w);
    }
    float bv = v[0]; int bk = kk[0];
    #pragma unroll
    for (int i = 1; i < NCAND; i++)
        if (v[i] < bv || (v[i] == bv && kk[i] < bk)) { bv = v[i]; bk = kk[i]; }
    int cnt = 0;
    #pragma unroll
    for (int i = 0; i < NCAND; i++) if (v[i] <= bv + MARGIN) cnt++;
    if (cnt > 1) {
        float bs = FLT_MAX; int bki = 0x7fffffff;
        for (int i = 0; i < NCAND; i++) {
            if (v[i] > bv + MARGIN) continue;
            int k = kk[i];
            bool dup = false;
            for (int j = 0; j < i; j++)
                if (v[j] <= bv + MARGIN && kk[j] == k) { dup = true; break; }
            if (dup) continue;
            float dot = 0.0f;
            const float* xr = x + (size_t)b * D_DIM;
            const float* er = e + (size_t)k * D_DIM;
            #pragma unroll 8
            for (int d = 0; d < D_DIM; d++) dot = fmaf(xr[d], er[d], dot);
            float s = g_c[k] - 2.0f * dot;
            if (s < bs || (s == bs && k < bki)) { bs = s; bki = k; }
        }
        bk = bki;
    }
    g_nmin[b] = bk;
    atomicAdd(&g_cnt[bk], 1);
}

// ---------------- phase B: z_q gather, losses, per-cluster x-sum (center only) ----------
__global__ void phaseb_kernel(const float* __restrict__ x, const float* __restrict__ e,
                              float* __restrict__ out) {
    const int warp = threadIdx.x >> 5;
    const int lane = threadIdx.x & 31;
    const int b = blockIdx.x * 8 + warp;

    int n  = g_nmin[b];
    int nx = n >> 5, ny = n & 31;
    int iu  = (nx < 31 ? nx + 1 : nx) * 32 + ny;
    int idn = (nx > 0  ? nx - 1 : nx) * 32 + ny;
    int il  = nx * 32 + (ny > 0  ? ny - 1 : ny);
    int ir  = nx * 32 + (ny < 31 ? ny + 1 : ny);
    int nbrs[4] = {iu, idn, il, ir};

    const float4* xr = (const float4*)(x + (size_t)b * D_DIM);
    const float4* zr = (const float4*)(e + (size_t)n * D_DIM);
    float4* zout = (float4*)out + (size_t)b * (D_DIM / 4);

    float commit = 0.f, som = 0.f;

    #pragma unroll
    for (int it = 0; it < 2; it++) {
        int q = lane + it * 32;
        float4 xv = xr[q];
        float4 zq = zr[q];
        zout[q] = zq;
        float4 dw = make_float4(xv.x - zq.x, xv.y - zq.y, xv.z - zq.z, xv.w - zq.w);
        commit += dw.x * dw.x + dw.y * dw.y + dw.z * dw.z + dw.w * dw.w;

        int base = n * D_DIM + q * 4;
        atomicAdd(&g_sumx[base + 0], xv.x);
        atomicAdd(&g_sumx[base + 1], xv.y);
        atomicAdd(&g_sumx[base + 2], xv.z);
        atomicAdd(&g_sumx[base + 3], xv.w);

        #pragma unroll
        for (int t = 0; t < 4; t++) {
            int nb = nbrs[t];
            float4 ev = ((const float4*)(e + (size_t)nb * D_DIM))[q];
            float d0 = xv.x - ev.x, d1 = xv.y - ev.y, d2 = xv.z - ev.z, d3 = xv.w - ev.w;
            som += d0 * d0 + d1 * d1 + d2 * d2 + d3 * d3;
        }
    }

    #pragma unroll
    for (int off = 16; off > 0; off >>= 1) {
        commit += __shfl_down_sync(0xffffffffu, commit, off);
        som    += __shfl_down_sync(0xffffffffu, som, off);
    }
    if (lane == 0) {
        atomicAdd(&g_commit, (double)commit);
        atomicAdd(&g_som, (double)som);
    }
}

// ---------------- finalize: reconstruct all 5 segment terms from S ----------------
// S[j][d] = sumx[j][d] - cnt[j]*e[j][d];  seg(idx_up)[k] = sum over inverse-up(k) of S.
__global__ void finalize_kernel(const float* __restrict__ e, float* __restrict__ out) {
    const size_t OFF = (size_t)B_ROWS * D_DIM;
    int i = blockIdx.x * 256 + threadIdx.x;   // K*D threads
    int k = i >> 8, d = i & 255;
    int kx = k >> 5, ky = k & 31;

    #define SVAL(j) (g_sumx[(j) * D_DIM + d] - (float)g_cnt[j] * e[(j) * D_DIM + d])

    float center = SVAL(k);
    float nbsum = 0.f;
    // inverse-up
    if (kx >= 1)  nbsum += SVAL(((kx - 1) << 5) | ky);
    if (kx == 31) nbsum += center;
    // inverse-down
    if (kx <= 30) nbsum += SVAL(((kx + 1) << 5) | ky);
    if (kx == 0)  nbsum += center;
    // inverse-left  (rows j with y_left(j) == ky)
    if (ky <= 30) nbsum += SVAL((kx << 5) | (ky + 1));
    if (ky == 0)  nbsum += center;
    // inverse-right (rows j with y_right(j) == ky)
    if (ky >= 1)  nbsum += SVAL((kx << 5) | (ky - 1));
    if (ky == 31) nbsum += center;

    out[OFF + 2 + i] = e[i] + LR_F * center + 0.5f * LR_F * nbsum;
    if (i == 0) {
        out[OFF]     = (float)(g_commit / ((double)B_ROWS * (double)D_DIM));
        out[OFF + 1] = (float)(g_som / ((double)B_ROWS * 4.0 * (double)D_DIM));
    }
    #undef SVAL
}

// ---------------- launch ----------------
extern "C" void kernel_launch(void* const* d_in, const int* in_sizes, int n_in,
                              void* d_out, int out_size) {
    const float* x = (const float*)d_in[0];
    const float* e = (const float*)d_in[1];
    float* out = (float*)d_out;

    prep_kernel<<<K_CL, 256>>>(e);
    convx_kernel<<<B_ROWS * D_DIM / 4 / 256, 256>>>(x);
    dim3 ggrid(NT, B_ROWS / TM);
    gemm_argmin_kernel<<<ggrid, 256, SMEMD>>>();
    select_kernel<<<B_ROWS / 256, 256>>>(x, e);
    phaseb_kernel<<<B_ROWS / 8, 256>>>(x, e, out);
    finalize_kernel<<<K_CL * D_DIM / 256, 256>>>(e, out);
}

// round 10
// speedup vs baseline: 2.9716x; 1.5662x over previous
#include <cuda_runtime.h>
#include <cuda_fp16.h>
#include <float.h>
#include <stdint.h>

#define B_ROWS 65536
#define K_CL   1024
#define D_DIM  256
#define LR_F   0.05f

#define TM     128        // CTA M tile
#define TN     128        // CTA N tile
#define NT     (K_CL / TN)   // 8 N-tiles
#define NCHUNK 8          // single fp16 pass: 8 chunks of K=32
#define ROWB   80         // padded smem row: 32 fp16 = 64B -> 80B (conflict-free LDSM)
#define ATILE  (TM * ROWB)          // 10240 B
#define SMEMD  (4 * ATILE)          // A0,A1,B0,B1 = 40960 B

// ---------------- device scratch ----------------
__device__ float   g_sumx[K_CL * D_DIM];   // per-cluster sum of x
__device__ int     g_cnt[K_CL];            // per-cluster row count
__device__ float   g_c[K_CL];              // ||e_k||^2
__device__ int     g_nmin[B_ROWS];
__device__ double  g_commit;
__device__ double  g_som;
__device__ __half  g_xh[B_ROWS * D_DIM];
__device__ __half  g_eh[K_CL * D_DIM];
__device__ float4  g_cand[(size_t)B_ROWS * NT];   // top-2 per (row, tile)

// ---------------- helpers ----------------
__device__ __forceinline__ uint32_t smem_u32(const void* p) {
    uint32_t a;
    asm("{ .reg .u64 t; cvta.to.shared.u64 t, %1; cvt.u32.u64 %0, t; }" : "=r"(a) : "l"(p));
    return a;
}
__device__ __forceinline__ void ldsm4(uint32_t* r, uint32_t addr) {
    asm volatile("ldmatrix.sync.aligned.m8n8.x4.shared.b16 {%0,%1,%2,%3}, [%4];"
        : "=r"(r[0]), "=r"(r[1]), "=r"(r[2]), "=r"(r[3]) : "r"(addr));
}
__device__ __forceinline__ void mma_f16(float* c, const uint32_t* a, const uint32_t* b) {
    asm volatile("mma.sync.aligned.m16n8k16.row.col.f32.f16.f16.f32 "
        "{%0,%1,%2,%3}, {%4,%5,%6,%7}, {%8,%9}, {%0,%1,%2,%3};"
        : "+f"(c[0]), "+f"(c[1]), "+f"(c[2]), "+f"(c[3])
        : "r"(a[0]), "r"(a[1]), "r"(a[2]), "r"(a[3]), "r"(b[0]), "r"(b[1]));
}
__device__ __forceinline__ bool lessc(float a, int ka, float b, int kb) {
    return a < b || (a == b && ka < kb);
}
__device__ __forceinline__ void merge2(float& bv, int& bk, float& sv, int& sk,
                                       float v, int k) {
    if (lessc(v, k, bv, bk)) { sv = bv; sk = bk; bv = v; bk = k; }
    else if (lessc(v, k, sv, sk)) { sv = v; sk = k; }
}

// ---------------- prep: zero sumx/cnt, c[k]=||e_k||^2, e -> fp16 ----------------
__global__ void prep_kernel(const float* __restrict__ e) {
    int k = blockIdx.x, t = threadIdx.x;
    int idx = k * D_DIM + t;
    g_sumx[idx] = 0.0f;
    float v = e[idx];
    g_eh[idx] = __float2half_rn(v);
    float sq = v * v;
    #pragma unroll
    for (int off = 16; off > 0; off >>= 1)
        sq += __shfl_down_sync(0xffffffffu, sq, off);
    __shared__ float ws[8];
    int lane = t & 31, wid = t >> 5;
    if (lane == 0) ws[wid] = sq;
    __syncthreads();
    if (t == 0) {
        float s = 0.f;
        #pragma unroll
        for (int i = 0; i < 8; i++) s += ws[i];
        g_c[k] = s;
        g_cnt[k] = 0;
        if (k == 0) { g_commit = 0.0; g_som = 0.0; }
    }
}

// ---------------- convert x to fp16 ----------------
__global__ void convx_kernel(const float* __restrict__ x) {
    int i = blockIdx.x * 256 + threadIdx.x;          // float4 index
    float4 v = ((const float4*)x)[i];
    __half2* xh2 = (__half2*)g_xh;
    xh2[i * 2]     = __halves2half2(__float2half_rn(v.x), __float2half_rn(v.y));
    xh2[i * 2 + 1] = __halves2half2(__float2half_rn(v.z), __float2half_rn(v.w));
}

// ---------------- mma.sync fp16 GEMM + top-2 argmin epilogue ----------------
// grid (NT, B_ROWS/TM) = (8, 512); 256 threads; warp grid 2(M) x 4(N), warp tile 64x32.
__global__ __launch_bounds__(256, 2) void gemm_argmin_kernel() {
    extern __shared__ __align__(128) char dsm[];
    __shared__ float cs[TN];

    const int tid = threadIdx.x;
    const int lane = tid & 31, wid = tid >> 5;
    const int wr = wid >> 2, wc = wid & 3;
    const int nt = blockIdx.x, n0 = nt * TN;
    const int m0 = blockIdx.y * TM;
    const uint32_t sb = smem_u32(dsm);

    if (tid < TN) cs[tid] = g_c[n0 + tid];

    // staging: 128 rows x 4 x uint4 per tile; thread does rows (tid>>2) and +64
    const int srow = tid >> 2, sq = tid & 3;

    // ldmatrix per-lane byte offsets within a tile
    const uint32_t aoff = (uint32_t)((wr * 64 + (lane & 15)) * ROWB + (lane >> 4) * 16);
    const uint32_t boff = (uint32_t)((wc * 32 + (lane & 7) + ((lane & 16) ? 8 : 0)) * ROWB
                                     + ((lane & 8) ? 16 : 0));

    float c[4][4][4];
    #pragma unroll
    for (int mi = 0; mi < 4; mi++)
        #pragma unroll
        for (int g = 0; g < 4; g++)
            #pragma unroll
            for (int e2 = 0; e2 < 4; e2++) c[mi][g][e2] = 0.f;

    // stage chunk 0 directly
    {
        #pragma unroll
        for (int i = 0; i < 2; i++) {
            int r = srow + i * 64;
            uint4 va = *(const uint4*)(g_xh + (size_t)(m0 + r) * D_DIM + sq * 8);
            *(uint4*)(dsm + r * ROWB + sq * 16) = va;
            uint4 vb = *(const uint4*)(g_eh + (size_t)(n0 + r) * D_DIM + sq * 8);
            *(uint4*)(dsm + 2 * ATILE + r * ROWB + sq * 16) = vb;
        }
    }
    __syncthreads();

    uint4 pa[2], pb[2];
    for (int ck = 0; ck < NCHUNK; ck++) {
        const int buf = ck & 1;

        if (ck < NCHUNK - 1) {
            const int d0 = (ck + 1) * 32;
            #pragma unroll
            for (int i = 0; i < 2; i++) {
                int r = srow + i * 64;
                pa[i] = *(const uint4*)(g_xh + (size_t)(m0 + r) * D_DIM + d0 + sq * 8);
                pb[i] = *(const uint4*)(g_eh + (size_t)(n0 + r) * D_DIM + d0 + sq * 8);
            }
        }

        const uint32_t aAdr = sb + buf * ATILE + aoff;
        const uint32_t bAdr = sb + 2 * ATILE + buf * ATILE + boff;
        #pragma unroll
        for (int kj = 0; kj < 2; kj++) {
            uint32_t af[4][4], bfr[2][4];
            #pragma unroll
            for (int mi = 0; mi < 4; mi++) ldsm4(af[mi], aAdr + mi * 16 * ROWB + kj * 32);
            #pragma unroll
            for (int gp = 0; gp < 2; gp++) ldsm4(bfr[gp], bAdr + gp * 16 * ROWB + kj * 32);
            #pragma unroll
            for (int mi = 0; mi < 4; mi++)
                #pragma unroll
                for (int g = 0; g < 4; g++)
                    mma_f16(c[mi][g], af[mi], &bfr[g >> 1][(g & 1) * 2]);
        }

        if (ck < NCHUNK - 1) {
            const int nb = (ck + 1) & 1;
            #pragma unroll
            for (int i = 0; i < 2; i++) {
                int r = srow + i * 64;
                *(uint4*)(dsm + nb * ATILE + r * ROWB + sq * 16) = pa[i];
                *(uint4*)(dsm + 2 * ATILE + nb * ATILE + r * ROWB + sq * 16) = pb[i];
            }
        }
        __syncthreads();
    }

    // ---- epilogue: per-row top-2 over this CTA's 128 cols ----
    float2* red = (float2*)dsm;   // [128 rows][4 wc][2 entries] — tiles are dead now

    #pragma unroll
    for (int mi = 0; mi < 4; mi++) {
        #pragma unroll
        for (int half = 0; half < 2; half++) {
            int rloc = wr * 64 + mi * 16 + (lane >> 2) + half * 8;
            float bv = FLT_MAX, sv = FLT_MAX;
            int bk = 0x7fffffff, sk = 0x7fffffff;
            #pragma unroll
            for (int g = 0; g < 4; g++) {
                #pragma unroll
                for (int e2 = 0; e2 < 2; e2++) {
                    int col = wc * 32 + g * 8 + (lane & 3) * 2 + e2;
                    float s = cs[col] - 2.0f * c[mi][g][half * 2 + e2];
                    merge2(bv, bk, sv, sk, s, n0 + col);
                }
            }
            #pragma unroll
            for (int off = 1; off <= 2; off <<= 1) {
                float obv = __shfl_xor_sync(0xffffffffu, bv, off);
                int   obk = __shfl_xor_sync(0xffffffffu, bk, off);
                float osv = __shfl_xor_sync(0xffffffffu, sv, off);
                int   osk = __shfl_xor_sync(0xffffffffu, sk, off);
                merge2(bv, bk, sv, sk, obv, obk);
                merge2(bv, bk, sv, sk, osv, osk);
            }
            if ((lane & 3) == 0) {
                red[(rloc * 4 + wc) * 2 + 0] = make_float2(bv, __int_as_float(bk));
                red[(rloc * 4 + wc) * 2 + 1] = make_float2(sv, __int_as_float(sk));
            }
        }
    }
    __syncthreads();

    if (tid < TM) {
        float bv = FLT_MAX, sv = FLT_MAX;
        int bk = 0x7fffffff, sk = 0x7fffffff;
        #pragma unroll
        for (int w = 0; w < 4; w++)
            #pragma unroll
            for (int p = 0; p < 2; p++) {
                float2 t = red[(tid * 4 + w) * 2 + p];
                merge2(bv, bk, sv, sk, t.x, __float_as_int(t.y));
            }
        g_cand[(size_t)(m0 + tid) * NT + nt] =
            make_float4(bv, __int_as_float(bk), sv, __int_as_float(sk));
    }
}

// ---------------- select: 8 lanes per row; near-ties rescored in EXACT fp32 ------------
// Rescore arithmetic bit-matches the known-passing full-fp32 kernel:
// dot = sequential fmaf chain; score = g_c[k] - 2*dot; lowest (tie -> lowest k).
#define MARGIN 0.05f
__global__ void select_kernel(const float* __restrict__ x, const float* __restrict__ e) {
    const int tid = threadIdx.x;
    const int l8 = tid & 7;                 // lane within 8-lane row group
    const int b = blockIdx.x * 32 + (tid >> 3);

    float4 c0 = g_cand[(size_t)b * NT + l8];
    float v0 = c0.x; int k0 = __float_as_int(c0.y);
    float v1 = c0.z; int k1 = __float_as_int(c0.w);

    float bv = v0; int bk = k0;
    if (lessc(v1, k1, bv, bk)) { bv = v1; bk = k1; }
    // min-reduce over 8-lane group
    #pragma unroll
    for (int off = 4; off > 0; off >>= 1) {
        float ov = __shfl_down_sync(0xffffffffu, bv, off, 8);
        int   ok = __shfl_down_sync(0xffffffffu, bk, off, 8);
        if (lessc(ov, ok, bv, bk)) { bv = ov; bk = ok; }
    }
    bv = __shfl_sync(0xffffffffu, bv, 0, 8);
    bk = __shfl_sync(0xffffffffu, bk, 0, 8);

    // count candidates within margin of approx min
    int cnt = (v0 <= bv + MARGIN ? 1 : 0) + (v1 <= bv + MARGIN ? 1 : 0);
    #pragma unroll
    for (int off = 4; off > 0; off >>= 1)
        cnt += __shfl_down_sync(0xffffffffu, cnt, off, 8);

    if (l8 == 0) {
        if (cnt > 1) {
            // exact fp32 rescore of all within-margin candidates (rare path)
            float bs = FLT_MAX; int bki = 0x7fffffff;
            const float* xr = x + (size_t)b * D_DIM;
            for (int t = 0; t < NT; t++) {
                float4 ct = g_cand[(size_t)b * NT + t];
                float vv[2] = {ct.x, ct.z};
                int   kv[2] = {__float_as_int(ct.y), __float_as_int(ct.w)};
                #pragma unroll
                for (int p = 0; p < 2; p++) {
                    if (vv[p] > bv + MARGIN) continue;
                    int k = kv[p];
                    float dot = 0.0f;
                    const float* er = e + (size_t)k * D_DIM;
                    #pragma unroll 8
                    for (int d = 0; d < D_DIM; d++) dot = fmaf(xr[d], er[d], dot);
                    float s = g_c[k] - 2.0f * dot;
                    if (s < bs || (s == bs && k < bki)) { bs = s; bki = k; }
                }
            }
            bk = bki;
        }
        g_nmin[b] = bk;
        atomicAdd(&g_cnt[bk], 1);
    }
}

// ---------------- phase B: z_q gather, losses, per-cluster x-sum (center only) ----------
__global__ void phaseb_kernel(const float* __restrict__ x, const float* __restrict__ e,
                              float* __restrict__ out) {
    const int warp = threadIdx.x >> 5;
    const int lane = threadIdx.x & 31;
    const int b = blockIdx.x * 8 + warp;

    int n  = g_nmin[b];
    int nx = n >> 5, ny = n & 31;
    int iu  = (nx < 31 ? nx + 1 : nx) * 32 + ny;
    int idn = (nx > 0  ? nx - 1 : nx) * 32 + ny;
    int il  = nx * 32 + (ny > 0  ? ny - 1 : ny);
    int ir  = nx * 32 + (ny < 31 ? ny + 1 : ny);
    int nbrs[4] = {iu, idn, il, ir};

    const float4* xr = (const float4*)(x + (size_t)b * D_DIM);
    const float4* zr = (const float4*)(e + (size_t)n * D_DIM);
    float4* zout = (float4*)out + (size_t)b * (D_DIM / 4);

    float commit = 0.f, som = 0.f;

    #pragma unroll
    for (int it = 0; it < 2; it++) {
        int q = lane + it * 32;
        float4 xv = xr[q];
        float4 zq = zr[q];
        zout[q] = zq;
        float4 dw = make_float4(xv.x - zq.x, xv.y - zq.y, xv.z - zq.z, xv.w - zq.w);
        commit += dw.x * dw.x + dw.y * dw.y + dw.z * dw.z + dw.w * dw.w;

        int base = n * D_DIM + q * 4;
        atomicAdd(&g_sumx[base + 0], xv.x);
        atomicAdd(&g_sumx[base + 1], xv.y);
        atomicAdd(&g_sumx[base + 2], xv.z);
        atomicAdd(&g_sumx[base + 3], xv.w);

        #pragma unroll
        for (int t = 0; t < 4; t++) {
            int nb = nbrs[t];
            float4 ev = ((const float4*)(e + (size_t)nb * D_DIM))[q];
            float d0 = xv.x - ev.x, d1 = xv.y - ev.y, d2 = xv.z - ev.z, d3 = xv.w - ev.w;
            som += d0 * d0 + d1 * d1 + d2 * d2 + d3 * d3;
        }
    }

    #pragma unroll
    for (int off = 16; off > 0; off >>= 1) {
        commit += __shfl_down_sync(0xffffffffu, commit, off);
        som    += __shfl_down_sync(0xffffffffu, som, off);
    }
    if (lane == 0) {
        atomicAdd(&g_commit, (double)commit);
        atomicAdd(&g_som, (double)som);
    }
}

// ---------------- finalize: reconstruct all 5 segment terms from S ----------------
// S[j][d] = sumx[j][d] - cnt[j]*e[j][d];  seg(idx_up)[k] = sum over inverse-up(k) of S.
__global__ void finalize_kernel(const float* __restrict__ e, float* __restrict__ out) {
    const size_t OFF = (size_t)B_ROWS * D_DIM;
    int i = blockIdx.x * 256 + threadIdx.x;   // K*D threads
    int k = i >> 8, d = i & 255;
    int kx = k >> 5, ky = k & 31;

    #define SVAL(j) (g_sumx[(j) * D_DIM + d] - (float)g_cnt[j] * e[(j) * D_DIM + d])

    float center = SVAL(k);
    float nbsum = 0.f;
    // inverse-up
    if (kx >= 1)  nbsum += SVAL(((kx - 1) << 5) | ky);
    if (kx == 31) nbsum += center;
    // inverse-down
    if (kx <= 30) nbsum += SVAL(((kx + 1) << 5) | ky);
    if (kx == 0)  nbsum += center;
    // inverse-left
    if (ky <= 30) nbsum += SVAL((kx << 5) | (ky + 1));
    if (ky == 0)  nbsum += center;
    // inverse-right
    if (ky >= 1)  nbsum += SVAL((kx << 5) | (ky - 1));
    if (ky == 31) nbsum += center;

    out[OFF + 2 + i] = e[i] + LR_F * center + 0.5f * LR_F * nbsum;
    if (i == 0) {
        out[OFF]     = (float)(g_commit / ((double)B_ROWS * (double)D_DIM));
        out[OFF + 1] = (float)(g_som / ((double)B_ROWS * 4.0 * (double)D_DIM));
    }
    #undef SVAL
}

// ---------------- launch ----------------
extern "C" void kernel_launch(void* const* d_in, const int* in_sizes, int n_in,
                              void* d_out, int out_size) {
    const float* x = (const float*)d_in[0];
    const float* e = (const float*)d_in[1];
    float* out = (float*)d_out;

    prep_kernel<<<K_CL, 256>>>(e);
    convx_kernel<<<B_ROWS * D_DIM / 4 / 256, 256>>>(x);
    dim3 ggrid(NT, B_ROWS / TM);
    gemm_argmin_kernel<<<ggrid, 256, SMEMD>>>();
    select_kernel<<<B_ROWS / 32, 256>>>(x, e);
    phaseb_kernel<<<B_ROWS / 8, 256>>>(x, e, out);
    finalize_kernel<<<K_CL * D_DIM / 256, 256>>>(e, out);
}